// round 5
// baseline (speedup 1.0000x reference)
#include <cuda_runtime.h>
#include <cuda_bf16.h>
#include <cstdint>

#define NSLOT 16
#define BATCH 4096
#define DIMN  1024

// ---------------- device scratch (allocation-free rule: __device__ globals) ----------------
__device__ __align__(1024) __nv_bfloat16 g_xhi[(size_t)NSLOT*BATCH*DIMN];
__device__ __align__(1024) __nv_bfloat16 g_xlo[(size_t)NSLOT*BATCH*DIMN];
__device__ __align__(1024) __nv_bfloat16 g_hhi[(size_t)NSLOT*BATCH*DIMN];
__device__ __align__(1024) __nv_bfloat16 g_hlo[(size_t)NSLOT*BATCH*DIMN];
__device__ __align__(1024) __nv_bfloat16 g_w1hi[(size_t)NSLOT*DIMN*DIMN];   // [n][k][d] K-major
__device__ __align__(1024) __nv_bfloat16 g_w1lo[(size_t)NSLOT*DIMN*DIMN];
__device__ __align__(1024) __nv_bfloat16 g_w2hi[(size_t)NSLOT*DIMN*DIMN];
__device__ __align__(1024) __nv_bfloat16 g_w2lo[(size_t)NSLOT*DIMN*DIMN];

// ---------------- baseline-ISA PTX helpers (sm_80-level, valid on target sm_100) ----------------
__device__ __forceinline__ uint32_t smem_to_u32(const void* p) {
    uint32_t a;
    asm("{ .reg .u64 t; cvta.to.shared.u64 t, %1; cvt.u32.u64 %0, t; }" : "=r"(a) : "l"(p));
    return a;
}
#define CP_ASYNC16(dst, src) \
    asm volatile("cp.async.cg.shared.global [%0], [%1], 16;" :: "r"(dst), "l"(src))
#define CP_COMMIT() asm volatile("cp.async.commit_group;" ::: "memory")
#define CP_WAIT1()  asm volatile("cp.async.wait_group 1;" ::: "memory")

#define LDSM4(r0, r1, r2, r3, addr) \
    asm volatile("ldmatrix.sync.aligned.m8n8.x4.shared.b16 {%0,%1,%2,%3}, [%4];" \
        : "=r"(r0), "=r"(r1), "=r"(r2), "=r"(r3) : "r"(addr))

#define MMA16816(d, a, b) \
    asm volatile("mma.sync.aligned.m16n8k16.row.col.f32.bf16.bf16.f32 " \
        "{%0,%1,%2,%3}, {%4,%5,%6,%7}, {%8,%9}, {%0,%1,%2,%3};" \
        : "+f"((d)[0]), "+f"((d)[1]), "+f"((d)[2]), "+f"((d)[3]) \
        : "r"((a)[0]), "r"((a)[1]), "r"((a)[2]), "r"((a)[3]), "r"((b)[0]), "r"((b)[1]))

__device__ __forceinline__ void splitf(float v, __nv_bfloat16& h, __nv_bfloat16& l) {
    h = __float2bfloat16(v);
    l = __float2bfloat16(v - __bfloat162float(h));
}
__device__ __forceinline__ uint32_t pack_bf(__nv_bfloat16 a, __nv_bfloat16 b) {
    __nv_bfloat162 t; t.x = a; t.y = b;
    return *reinterpret_cast<uint32_t*>(&t);
}

// ---------------- LayerNorm + hi/lo split, [b][n][d] -> [n][b][d] ----------------
__global__ void __launch_bounds__(256) ln_split_kernel(
    const float* __restrict__ x, const float* __restrict__ gamma, const float* __restrict__ beta,
    __nv_bfloat16* __restrict__ xhi, __nv_bfloat16* __restrict__ xlo)
{
    int warp = threadIdx.x >> 5, lane = threadIdx.x & 31;
    long r = (long)blockIdx.x * 8 + warp;           // row = b*16+n
    int b = (int)(r >> 4), n = (int)(r & 15);
    const float4* xr = (const float4*)(x + (size_t)r * DIMN);
    float4 v[8]; float s = 0.f, ss = 0.f;
#pragma unroll
    for (int i = 0; i < 8; i++) {
        v[i] = xr[lane + 32 * i];
        s  += v[i].x + v[i].y + v[i].z + v[i].w;
        ss += v[i].x * v[i].x + v[i].y * v[i].y + v[i].z * v[i].z + v[i].w * v[i].w;
    }
#pragma unroll
    for (int o = 16; o > 0; o >>= 1) {
        s  += __shfl_xor_sync(0xFFFFFFFFu, s, o);
        ss += __shfl_xor_sync(0xFFFFFFFFu, ss, o);
    }
    float mu = s * (1.f / DIMN);
    float var = ss * (1.f / DIMN) - mu * mu;
    float rs = rsqrtf(var + 1e-5f);
    size_t ob = ((size_t)n * BATCH + b) * DIMN;
    uint2* oh = (uint2*)(xhi + ob); uint2* ol = (uint2*)(xlo + ob);
    const float* gm = gamma + (size_t)n * DIMN;
    const float* bt = beta  + (size_t)n * DIMN;
#pragma unroll
    for (int i = 0; i < 8; i++) {
        int d0 = (lane + 32 * i) * 4;
        float y0 = (v[i].x - mu) * rs * gm[d0 + 0] + bt[d0 + 0];
        float y1 = (v[i].y - mu) * rs * gm[d0 + 1] + bt[d0 + 1];
        float y2 = (v[i].z - mu) * rs * gm[d0 + 2] + bt[d0 + 2];
        float y3 = (v[i].w - mu) * rs * gm[d0 + 3] + bt[d0 + 3];
        __nv_bfloat16 h0,l0,h1,l1,h2,l2,h3,l3;
        splitf(y0,h0,l0); splitf(y1,h1,l1); splitf(y2,h2,l2); splitf(y3,h3,l3);
        uint2 ph, pl;
        ph.x = pack_bf(h0,h1); ph.y = pack_bf(h2,h3);
        pl.x = pack_bf(l0,l1); pl.y = pack_bf(l2,l3);
        oh[lane + 32 * i] = ph; ol[lane + 32 * i] = pl;
    }
}

// ---------------- W[n][d][k] -> Wt[n][k][d] hi/lo (transpose + split) ----------------
__global__ void __launch_bounds__(256) wprep_kernel(
    const float* __restrict__ W, __nv_bfloat16* __restrict__ hi, __nv_bfloat16* __restrict__ lo)
{
    __shared__ float t[32][33];
    int n = blockIdx.z;
    int d0 = blockIdx.x * 32, k0 = blockIdx.y * 32;
    const float* Wn = W + (size_t)n * DIMN * DIMN;
#pragma unroll
    for (int j = 0; j < 32; j += 8)
        t[threadIdx.y + j][threadIdx.x] = Wn[(size_t)(d0 + threadIdx.y + j) * DIMN + k0 + threadIdx.x];
    __syncthreads();
    size_t base = (size_t)n * DIMN * DIMN;
#pragma unroll
    for (int j = 0; j < 32; j += 8) {
        float vv = t[threadIdx.x][threadIdx.y + j];
        __nv_bfloat16 h, l; splitf(vv, h, l);
        size_t idx = base + (size_t)(k0 + threadIdx.y + j) * DIMN + d0 + threadIdx.x;
        hi[idx] = h; lo[idx] = l;
    }
}

// ---------------- split-bf16 GEMM via mma.sync (3 passes: hh, hl, lh) ----------------
// CTA tile 128x128, BK=32. 256 threads = 8 warps in 2(m)x4(n) grid, warp tile 64x32.
// 4 warps/SMSP at 2 CTAs/SM -> tensor pipe stays fed through LDSM/sync phases.
#define BK 32
#define NCHUNK (DIMN / BK)          // 32
#define ROWPITCH 80                 // 64B data + 16B pad -> conflict-free ldmatrix
#define TILEB (128 * ROWPITCH)      // 10240
#define STAGEB (4 * TILEB)          // 40960
#define SMEM_GEMM (2 * STAGEB)      // 81920

template<int EPI>
__global__ void __launch_bounds__(256, 2) gemm_split_kernel(
    const __nv_bfloat16* __restrict__ Ahi, const __nv_bfloat16* __restrict__ Alo,
    const __nv_bfloat16* __restrict__ Bhi, const __nv_bfloat16* __restrict__ Blo,
    const float* __restrict__ bias,
    float* __restrict__ outF,
    __nv_bfloat16* __restrict__ outHi, __nv_bfloat16* __restrict__ outLo)
{
    extern __shared__ __align__(1024) char smem[];
    uint32_t sb = smem_to_u32(smem);
    const int tid = threadIdx.x, wid = tid >> 5, lane = tid & 31;
    const int nt = blockIdx.x, mt = blockIdx.y, slot = blockIdx.z;
    const int warp_m = wid & 1, warp_n = wid >> 1;   // 2 x 4 warp grid

    const size_t arow0 = (size_t)slot * BATCH + (size_t)mt * 128;  // rows in [n*b][d]
    const size_t brow0 = (size_t)slot * DIMN  + (size_t)nt * 128;  // rows in [n*k][d]

    const __nv_bfloat16* srcs[4] = {
        Ahi + arow0 * DIMN, Alo + arow0 * DIMN,
        Bhi + brow0 * DIMN, Blo + brow0 * DIMN };

    // fill one pipeline stage for k-chunk c: 2048 x 16B cp.async, 8 per thread
    auto fill = [&](int s, int c) {
#pragma unroll
        for (int j = 0; j < 8; j++) {
            int i = tid + j * 256;
            int tile = i >> 9;             // 0..3 (constant per unrolled j)
            int row  = (i >> 2) & 127;
            int ch   = i & 3;              // 16B chunk within 64B row
            uint32_t dst = sb + s * STAGEB + tile * TILEB + row * ROWPITCH + ch * 16;
            const __nv_bfloat16* src = srcs[tile] + (size_t)row * DIMN + c * BK + ch * 8;
            CP_ASYNC16(dst, src);
        }
    };

    float acc[4][4][4];
#pragma unroll
    for (int tm = 0; tm < 4; tm++)
#pragma unroll
        for (int f = 0; f < 4; f++)
#pragma unroll
            for (int q = 0; q < 4; q++) acc[tm][f][q] = 0.f;

    fill(0, 0); CP_COMMIT();
    fill(1, 1); CP_COMMIT();

    for (int c = 0; c < NCHUNK; c++) {
        CP_WAIT1();
        __syncthreads();
        const int s = c & 1;
        const uint32_t sAh = sb + s * STAGEB;
        const uint32_t sAl = sAh + TILEB;
        const uint32_t sBh = sAl + TILEB;
        const uint32_t sBl = sBh + TILEB;

#pragma unroll
        for (int ks = 0; ks < 2; ks++) {
            uint32_t ah[4][4], al[4][4];
            const uint32_t acoff = ks * 32 + ((lane >> 4) << 4);
#pragma unroll
            for (int tm = 0; tm < 4; tm++) {
                uint32_t r = warp_m * 64 + tm * 16 + (lane & 15);
                LDSM4(ah[tm][0], ah[tm][1], ah[tm][2], ah[tm][3], sAh + r * ROWPITCH + acoff);
                LDSM4(al[tm][0], al[tm][1], al[tm][2], al[tm][3], sAl + r * ROWPITCH + acoff);
            }
            uint32_t bh[4][2], bl[4][2];
            const uint32_t bcoff = ks * 32 + (((lane >> 3) & 1) << 4);
#pragma unroll
            for (int g = 0; g < 2; g++) {
                uint32_t n = warp_n * 32 + g * 16 + (lane & 7) + ((lane >> 4) << 3);
                LDSM4(bh[2*g][0], bh[2*g][1], bh[2*g+1][0], bh[2*g+1][1], sBh + n * ROWPITCH + bcoff);
                LDSM4(bl[2*g][0], bl[2*g][1], bl[2*g+1][0], bl[2*g+1][1], sBl + n * ROWPITCH + bcoff);
            }
#pragma unroll
            for (int tm = 0; tm < 4; tm++)
#pragma unroll
                for (int f = 0; f < 4; f++) {
                    MMA16816(acc[tm][f], ah[tm], bh[f]);
                    MMA16816(acc[tm][f], ah[tm], bl[f]);
                    MMA16816(acc[tm][f], al[tm], bh[f]);
                }
        }
        __syncthreads();
        if (c + 2 < NCHUNK) fill(s, c + 2);
        CP_COMMIT();   // always commit to keep wait_group counting aligned
    }

    // ---------------- epilogue: straight from register accumulators ----------------
#pragma unroll
    for (int tm = 0; tm < 4; tm++) {
#pragma unroll
        for (int f = 0; f < 4; f++) {
            int grow = mt * 128 + warp_m * 64 + tm * 16 + (lane >> 2);
            int ncol = nt * 128 + warp_n * 32 + f * 8 + (lane & 3) * 2;
            float bia0 = __ldg(bias + (size_t)slot * DIMN + ncol);
            float bia1 = __ldg(bias + (size_t)slot * DIMN + ncol + 1);
            float v00 = acc[tm][f][0] + bia0, v01 = acc[tm][f][1] + bia1;  // row grow
            float v10 = acc[tm][f][2] + bia0, v11 = acc[tm][f][3] + bia1;  // row grow+8
            if (EPI == 1) {
                const float is2 = 0.70710678118654752f;
                v00 = 0.5f * v00 * (1.0f + erff(v00 * is2));
                v01 = 0.5f * v01 * (1.0f + erff(v01 * is2));
                v10 = 0.5f * v10 * (1.0f + erff(v10 * is2));
                v11 = 0.5f * v11 * (1.0f + erff(v11 * is2));
                __nv_bfloat16 h00,l00,h01,l01,h10,l10,h11,l11;
                splitf(v00,h00,l00); splitf(v01,h01,l01);
                splitf(v10,h10,l10); splitf(v11,h11,l11);
                size_t o0 = ((size_t)slot * BATCH + grow) * DIMN + ncol;
                size_t o1 = o0 + 8 * DIMN;
                *(uint32_t*)(outHi + o0) = pack_bf(h00, h01);
                *(uint32_t*)(outLo + o0) = pack_bf(l00, l01);
                *(uint32_t*)(outHi + o1) = pack_bf(h10, h11);
                *(uint32_t*)(outLo + o1) = pack_bf(l10, l11);
            } else {
                size_t o0 = ((size_t)grow * NSLOT + slot) * DIMN + ncol;
                size_t o1 = (((size_t)grow + 8) * NSLOT + slot) * DIMN + ncol;
                float2 w0; w0.x = v00; w0.y = v01;
                float2 w1; w1.x = v10; w1.y = v11;
                *(float2*)(outF + o0) = w0;
                *(float2*)(outF + o1) = w1;
            }
        }
    }
}

// ---------------- host ----------------
extern "C" void kernel_launch(void* const* d_in, const int* in_sizes, int n_in,
                              void* d_out, int out_size) {
    (void)in_sizes; (void)n_in; (void)out_size;
    const float* x     = (const float*)d_in[0];
    const float* gamma = (const float*)d_in[1];
    const float* beta  = (const float*)d_in[2];
    const float* W1    = (const float*)d_in[3];
    const float* b1    = (const float*)d_in[4];
    const float* W2    = (const float*)d_in[5];
    const float* b2    = (const float*)d_in[6];
    float* out = (float*)d_out;

    void *pxhi, *pxlo, *phhi, *phlo, *pw1h, *pw1l, *pw2h, *pw2l;
    cudaGetSymbolAddress(&pxhi, g_xhi);  cudaGetSymbolAddress(&pxlo, g_xlo);
    cudaGetSymbolAddress(&phhi, g_hhi);  cudaGetSymbolAddress(&phlo, g_hlo);
    cudaGetSymbolAddress(&pw1h, g_w1hi); cudaGetSymbolAddress(&pw1l, g_w1lo);
    cudaGetSymbolAddress(&pw2h, g_w2hi); cudaGetSymbolAddress(&pw2l, g_w2lo);

    cudaFuncSetAttribute(gemm_split_kernel<1>, cudaFuncAttributeMaxDynamicSharedMemorySize, SMEM_GEMM);
    cudaFuncSetAttribute(gemm_split_kernel<2>, cudaFuncAttributeMaxDynamicSharedMemorySize, SMEM_GEMM);

    ln_split_kernel<<<(NSLOT * BATCH) / 8, 256>>>(x, gamma, beta,
        (__nv_bfloat16*)pxhi, (__nv_bfloat16*)pxlo);
    wprep_kernel<<<dim3(32, 32, NSLOT), dim3(32, 8)>>>(W1, (__nv_bfloat16*)pw1h, (__nv_bfloat16*)pw1l);
    wprep_kernel<<<dim3(32, 32, NSLOT), dim3(32, 8)>>>(W2, (__nv_bfloat16*)pw2h, (__nv_bfloat16*)pw2l);

    dim3 grid(DIMN / 128, BATCH / 128, NSLOT);   // (8, 32, 16) = 4096 CTAs
    gemm_split_kernel<1><<<grid, 256, SMEM_GEMM>>>(
        (const __nv_bfloat16*)pxhi, (const __nv_bfloat16*)pxlo,
        (const __nv_bfloat16*)pw1h, (const __nv_bfloat16*)pw1l,
        b1, nullptr, (__nv_bfloat16*)phhi, (__nv_bfloat16*)phlo);
    gemm_split_kernel<2><<<grid, 256, SMEM_GEMM>>>(
        (const __nv_bfloat16*)phhi, (const __nv_bfloat16*)phlo,
        (const __nv_bfloat16*)pw2h, (const __nv_bfloat16*)pw2l,
        b2, out, nullptr, nullptr);
}

// round 6
// speedup vs baseline: 1.1306x; 1.1306x over previous
#include <cuda_runtime.h>
#include <cuda_bf16.h>
#include <cstdint>

#define NSLOT 16
#define BATCH 4096
#define DIMN  1024

// ---------------- device scratch (allocation-free rule: __device__ globals) ----------------
__device__ __align__(1024) __nv_bfloat16 g_xhi[(size_t)NSLOT*BATCH*DIMN];
__device__ __align__(1024) __nv_bfloat16 g_xlo[(size_t)NSLOT*BATCH*DIMN];
__device__ __align__(1024) __nv_bfloat16 g_hhi[(size_t)NSLOT*BATCH*DIMN];
__device__ __align__(1024) __nv_bfloat16 g_hlo[(size_t)NSLOT*BATCH*DIMN];
__device__ __align__(1024) __nv_bfloat16 g_w1hi[(size_t)NSLOT*DIMN*DIMN];   // [n][k][d] K-major
__device__ __align__(1024) __nv_bfloat16 g_w1lo[(size_t)NSLOT*DIMN*DIMN];
__device__ __align__(1024) __nv_bfloat16 g_w2hi[(size_t)NSLOT*DIMN*DIMN];
__device__ __align__(1024) __nv_bfloat16 g_w2lo[(size_t)NSLOT*DIMN*DIMN];

// ---------------- baseline-ISA PTX helpers (sm_80-level, valid on target sm_100) ----------------
__device__ __forceinline__ uint32_t smem_to_u32(const void* p) {
    uint32_t a;
    asm("{ .reg .u64 t; cvta.to.shared.u64 t, %1; cvt.u32.u64 %0, t; }" : "=r"(a) : "l"(p));
    return a;
}
#define CP_ASYNC16(dst, src) \
    asm volatile("cp.async.cg.shared.global [%0], [%1], 16;" :: "r"(dst), "l"(src))
#define CP_COMMIT() asm volatile("cp.async.commit_group;" ::: "memory")
#define CP_WAIT1()  asm volatile("cp.async.wait_group 1;" ::: "memory")

#define LDSM4(r0, r1, r2, r3, addr) \
    asm volatile("ldmatrix.sync.aligned.m8n8.x4.shared.b16 {%0,%1,%2,%3}, [%4];" \
        : "=r"(r0), "=r"(r1), "=r"(r2), "=r"(r3) : "r"(addr))

#define MMA16816(d, a, b) \
    asm volatile("mma.sync.aligned.m16n8k16.row.col.f32.bf16.bf16.f32 " \
        "{%0,%1,%2,%3}, {%4,%5,%6,%7}, {%8,%9}, {%0,%1,%2,%3};" \
        : "+f"((d)[0]), "+f"((d)[1]), "+f"((d)[2]), "+f"((d)[3]) \
        : "r"((a)[0]), "r"((a)[1]), "r"((a)[2]), "r"((a)[3]), "r"((b)[0]), "r"((b)[1]))

__device__ __forceinline__ void splitf(float v, __nv_bfloat16& h, __nv_bfloat16& l) {
    h = __float2bfloat16(v);
    l = __float2bfloat16(v - __bfloat162float(h));
}
__device__ __forceinline__ uint32_t pack_bf(__nv_bfloat16 a, __nv_bfloat16 b) {
    __nv_bfloat162 t; t.x = a; t.y = b;
    return *reinterpret_cast<uint32_t*>(&t);
}

// ---------------- LayerNorm + hi/lo split, [b][n][d] -> [n][b][d] ----------------
__global__ void __launch_bounds__(256) ln_split_kernel(
    const float* __restrict__ x, const float* __restrict__ gamma, const float* __restrict__ beta,
    __nv_bfloat16* __restrict__ xhi, __nv_bfloat16* __restrict__ xlo)
{
    int warp = threadIdx.x >> 5, lane = threadIdx.x & 31;
    long r = (long)blockIdx.x * 8 + warp;           // row = b*16+n
    int b = (int)(r >> 4), n = (int)(r & 15);
    const float4* xr = (const float4*)(x + (size_t)r * DIMN);
    float4 v[8]; float s = 0.f, ss = 0.f;
#pragma unroll
    for (int i = 0; i < 8; i++) {
        v[i] = xr[lane + 32 * i];
        s  += v[i].x + v[i].y + v[i].z + v[i].w;
        ss += v[i].x * v[i].x + v[i].y * v[i].y + v[i].z * v[i].z + v[i].w * v[i].w;
    }
#pragma unroll
    for (int o = 16; o > 0; o >>= 1) {
        s  += __shfl_xor_sync(0xFFFFFFFFu, s, o);
        ss += __shfl_xor_sync(0xFFFFFFFFu, ss, o);
    }
    float mu = s * (1.f / DIMN);
    float var = ss * (1.f / DIMN) - mu * mu;
    float rs = rsqrtf(var + 1e-5f);
    size_t ob = ((size_t)n * BATCH + b) * DIMN;
    uint2* oh = (uint2*)(xhi + ob); uint2* ol = (uint2*)(xlo + ob);
    const float* gm = gamma + (size_t)n * DIMN;
    const float* bt = beta  + (size_t)n * DIMN;
#pragma unroll
    for (int i = 0; i < 8; i++) {
        int d0 = (lane + 32 * i) * 4;
        float y0 = (v[i].x - mu) * rs * gm[d0 + 0] + bt[d0 + 0];
        float y1 = (v[i].y - mu) * rs * gm[d0 + 1] + bt[d0 + 1];
        float y2 = (v[i].z - mu) * rs * gm[d0 + 2] + bt[d0 + 2];
        float y3 = (v[i].w - mu) * rs * gm[d0 + 3] + bt[d0 + 3];
        __nv_bfloat16 h0,l0,h1,l1,h2,l2,h3,l3;
        splitf(y0,h0,l0); splitf(y1,h1,l1); splitf(y2,h2,l2); splitf(y3,h3,l3);
        uint2 ph, pl;
        ph.x = pack_bf(h0,h1); ph.y = pack_bf(h2,h3);
        pl.x = pack_bf(l0,l1); pl.y = pack_bf(l2,l3);
        oh[lane + 32 * i] = ph; ol[lane + 32 * i] = pl;
    }
}

// ---------------- W[n][d][k] -> Wt[n][k][d] hi/lo (transpose + split) ----------------
__global__ void __launch_bounds__(256) wprep_kernel(
    const float* __restrict__ W, __nv_bfloat16* __restrict__ hi, __nv_bfloat16* __restrict__ lo)
{
    __shared__ float t[32][33];
    int n = blockIdx.z;
    int d0 = blockIdx.x * 32, k0 = blockIdx.y * 32;
    const float* Wn = W + (size_t)n * DIMN * DIMN;
#pragma unroll
    for (int j = 0; j < 32; j += 8)
        t[threadIdx.y + j][threadIdx.x] = Wn[(size_t)(d0 + threadIdx.y + j) * DIMN + k0 + threadIdx.x];
    __syncthreads();
    size_t base = (size_t)n * DIMN * DIMN;
#pragma unroll
    for (int j = 0; j < 32; j += 8) {
        float vv = t[threadIdx.x][threadIdx.y + j];
        __nv_bfloat16 h, l; splitf(vv, h, l);
        size_t idx = base + (size_t)(k0 + threadIdx.y + j) * DIMN + d0 + threadIdx.x;
        hi[idx] = h; lo[idx] = l;
    }
}

// ---------------- split-bf16 GEMM via mma.sync (3 terms: hh, hl, lh) ----------------
// CTA tile 128x128, BK=32. 256 threads = 8 warps in 2(m)x4(n) grid, warp tile 64x32.
// 3-stage cp.async pipeline, ONE barrier per chunk, prefetch distance 2.
// Compact 64B-pitch XOR-swizzled smem layout (chunk' = chunk ^ ((row>>1)&3)).
#define BK 32
#define NCHUNK (DIMN / BK)          // 32
#define TILEB (128 * 64)            // 8192 bytes per operand tile
#define STAGEB (4 * TILEB)          // 32768
#define NSTAGE 3
#define SMEM_GEMM (NSTAGE * STAGEB) // 98304

__device__ __forceinline__ uint32_t swz(uint32_t row, uint32_t chunk) {
    return row * 64 + ((chunk ^ ((row >> 1) & 3)) << 4);
}

template<int EPI>
__global__ void __launch_bounds__(256, 2) gemm_split_kernel(
    const __nv_bfloat16* __restrict__ Ahi, const __nv_bfloat16* __restrict__ Alo,
    const __nv_bfloat16* __restrict__ Bhi, const __nv_bfloat16* __restrict__ Blo,
    const float* __restrict__ bias,
    float* __restrict__ outF,
    __nv_bfloat16* __restrict__ outHi, __nv_bfloat16* __restrict__ outLo)
{
    extern __shared__ __align__(1024) char smem[];
    uint32_t sb = smem_to_u32(smem);
    const int tid = threadIdx.x, wid = tid >> 5, lane = tid & 31;
    const int nt = blockIdx.x, mt = blockIdx.y, slot = blockIdx.z;
    const int warp_m = wid & 1, warp_n = wid >> 1;   // 2 x 4 warp grid

    const size_t arow0 = (size_t)slot * BATCH + (size_t)mt * 128;  // rows in [n*b][d]
    const size_t brow0 = (size_t)slot * DIMN  + (size_t)nt * 128;  // rows in [n*k][d]

    const __nv_bfloat16* srcs[4] = {
        Ahi + arow0 * DIMN, Alo + arow0 * DIMN,
        Bhi + brow0 * DIMN, Blo + brow0 * DIMN };

    // fill one pipeline stage for k-chunk c: 2048 x 16B cp.async, 8 per thread
    auto fill = [&](int s, int c) {
#pragma unroll
        for (int j = 0; j < 8; j++) {
            int i = tid + j * 256;
            int tile = i >> 9;             // 0..3 (constant per unrolled j)
            int row  = (i >> 2) & 127;
            int ch   = i & 3;              // logical 16B chunk within 64B row
            uint32_t dst = sb + s * STAGEB + tile * TILEB + swz(row, ch);
            const __nv_bfloat16* src = srcs[tile] + (size_t)row * DIMN + c * BK + ch * 8;
            CP_ASYNC16(dst, src);
        }
    };

    float acc[4][4][4];
#pragma unroll
    for (int tm = 0; tm < 4; tm++)
#pragma unroll
        for (int f = 0; f < 4; f++)
#pragma unroll
            for (int q = 0; q < 4; q++) acc[tm][f][q] = 0.f;

    fill(0, 0); CP_COMMIT();
    fill(1, 1); CP_COMMIT();

    for (int c = 0; c < NCHUNK; c++) {
        CP_WAIT1();          // group for chunk c complete (only c+1 may pend)
        __syncthreads();     // all warps done with chunk c-1 -> its stage is free
        if (c + 2 < NCHUNK) { fill((c + 2) % NSTAGE, c + 2); CP_COMMIT(); }

        const uint32_t stg = sb + (c % NSTAGE) * STAGEB;
        const uint32_t sAh = stg;
        const uint32_t sAl = stg + TILEB;
        const uint32_t sBh = stg + 2 * TILEB;
        const uint32_t sBl = stg + 3 * TILEB;

#pragma unroll
        for (int ks = 0; ks < 2; ks++) {
            uint32_t ah[4][4], al[4][4];
            const uint32_t ca = ks * 2 + (lane >> 4);
#pragma unroll
            for (int tm = 0; tm < 4; tm++) {
                uint32_t r = warp_m * 64 + tm * 16 + (lane & 15);
                LDSM4(ah[tm][0], ah[tm][1], ah[tm][2], ah[tm][3], sAh + swz(r, ca));
                LDSM4(al[tm][0], al[tm][1], al[tm][2], al[tm][3], sAl + swz(r, ca));
            }
            uint32_t bh[4][2], bl[4][2];
            const uint32_t cb = ks * 2 + ((lane >> 3) & 1);
#pragma unroll
            for (int g = 0; g < 2; g++) {
                uint32_t n = warp_n * 32 + g * 16 + (lane & 7) + ((lane >> 4) << 3);
                LDSM4(bh[2*g][0], bh[2*g][1], bh[2*g+1][0], bh[2*g+1][1], sBh + swz(n, cb));
                LDSM4(bl[2*g][0], bl[2*g][1], bl[2*g+1][0], bl[2*g+1][1], sBl + swz(n, cb));
            }
#pragma unroll
            for (int tm = 0; tm < 4; tm++)
#pragma unroll
                for (int f = 0; f < 4; f++) {
                    MMA16816(acc[tm][f], ah[tm], bh[f]);
                    MMA16816(acc[tm][f], ah[tm], bl[f]);
                    MMA16816(acc[tm][f], al[tm], bh[f]);
                }
        }
    }

    // ---------------- epilogue: straight from register accumulators ----------------
#pragma unroll
    for (int tm = 0; tm < 4; tm++) {
#pragma unroll
        for (int f = 0; f < 4; f++) {
            int grow = mt * 128 + warp_m * 64 + tm * 16 + (lane >> 2);
            int ncol = nt * 128 + warp_n * 32 + f * 8 + (lane & 3) * 2;
            float bia0 = __ldg(bias + (size_t)slot * DIMN + ncol);
            float bia1 = __ldg(bias + (size_t)slot * DIMN + ncol + 1);
            float v00 = acc[tm][f][0] + bia0, v01 = acc[tm][f][1] + bia1;  // row grow
            float v10 = acc[tm][f][2] + bia0, v11 = acc[tm][f][3] + bia1;  // row grow+8
            if (EPI == 1) {
                const float is2 = 0.70710678118654752f;
                v00 = 0.5f * v00 * (1.0f + erff(v00 * is2));
                v01 = 0.5f * v01 * (1.0f + erff(v01 * is2));
                v10 = 0.5f * v10 * (1.0f + erff(v10 * is2));
                v11 = 0.5f * v11 * (1.0f + erff(v11 * is2));
                __nv_bfloat16 h00,l00,h01,l01,h10,l10,h11,l11;
                splitf(v00,h00,l00); splitf(v01,h01,l01);
                splitf(v10,h10,l10); splitf(v11,h11,l11);
                size_t o0 = ((size_t)slot * BATCH + grow) * DIMN + ncol;
                size_t o1 = o0 + 8 * DIMN;
                *(uint32_t*)(outHi + o0) = pack_bf(h00, h01);
                *(uint32_t*)(outLo + o0) = pack_bf(l00, l01);
                *(uint32_t*)(outHi + o1) = pack_bf(h10, h11);
                *(uint32_t*)(outLo + o1) = pack_bf(l10, l11);
            } else {
                size_t o0 = ((size_t)grow * NSLOT + slot) * DIMN + ncol;
                size_t o1 = (((size_t)grow + 8) * NSLOT + slot) * DIMN + ncol;
                float2 w0; w0.x = v00; w0.y = v01;
                float2 w1; w1.x = v10; w1.y = v11;
                *(float2*)(outF + o0) = w0;
                *(float2*)(outF + o1) = w1;
            }
        }
    }
}

// ---------------- host ----------------
extern "C" void kernel_launch(void* const* d_in, const int* in_sizes, int n_in,
                              void* d_out, int out_size) {
    (void)in_sizes; (void)n_in; (void)out_size;
    const float* x     = (const float*)d_in[0];
    const float* gamma = (const float*)d_in[1];
    const float* beta  = (const float*)d_in[2];
    const float* W1    = (const float*)d_in[3];
    const float* b1    = (const float*)d_in[4];
    const float* W2    = (const float*)d_in[5];
    const float* b2    = (const float*)d_in[6];
    float* out = (float*)d_out;

    void *pxhi, *pxlo, *phhi, *phlo, *pw1h, *pw1l, *pw2h, *pw2l;
    cudaGetSymbolAddress(&pxhi, g_xhi);  cudaGetSymbolAddress(&pxlo, g_xlo);
    cudaGetSymbolAddress(&phhi, g_hhi);  cudaGetSymbolAddress(&phlo, g_hlo);
    cudaGetSymbolAddress(&pw1h, g_w1hi); cudaGetSymbolAddress(&pw1l, g_w1lo);
    cudaGetSymbolAddress(&pw2h, g_w2hi); cudaGetSymbolAddress(&pw2l, g_w2lo);

    cudaFuncSetAttribute(gemm_split_kernel<1>, cudaFuncAttributeMaxDynamicSharedMemorySize, SMEM_GEMM);
    cudaFuncSetAttribute(gemm_split_kernel<2>, cudaFuncAttributeMaxDynamicSharedMemorySize, SMEM_GEMM);

    ln_split_kernel<<<(NSLOT * BATCH) / 8, 256>>>(x, gamma, beta,
        (__nv_bfloat16*)pxhi, (__nv_bfloat16*)pxlo);
    wprep_kernel<<<dim3(32, 32, NSLOT), dim3(32, 8)>>>(W1, (__nv_bfloat16*)pw1h, (__nv_bfloat16*)pw1l);
    wprep_kernel<<<dim3(32, 32, NSLOT), dim3(32, 8)>>>(W2, (__nv_bfloat16*)pw2h, (__nv_bfloat16*)pw2l);

    dim3 grid(DIMN / 128, BATCH / 128, NSLOT);   // (8, 32, 16) = 4096 CTAs
    gemm_split_kernel<1><<<grid, 256, SMEM_GEMM>>>(
        (const __nv_bfloat16*)pxhi, (const __nv_bfloat16*)pxlo,
        (const __nv_bfloat16*)pw1h, (const __nv_bfloat16*)pw1l,
        b1, nullptr, (__nv_bfloat16*)phhi, (__nv_bfloat16*)phlo);
    gemm_split_kernel<2><<<grid, 256, SMEM_GEMM>>>(
        (const __nv_bfloat16*)phhi, (const __nv_bfloat16*)phlo,
        (const __nv_bfloat16*)pw2h, (const __nv_bfloat16*)pw2l,
        b2, out, nullptr, nullptr);
}

// round 7
// speedup vs baseline: 1.2718x; 1.1250x over previous
#include <cuda_runtime.h>
#include <cuda.h>
#include <cuda_bf16.h>
#include <cstdint>

#define NSLOT 16
#define BATCH 4096
#define DIMN  1024

// ---------------- device scratch (allocation-free rule: __device__ globals) ----------------
__device__ __align__(1024) __nv_bfloat16 g_xhi[(size_t)NSLOT*BATCH*DIMN];
__device__ __align__(1024) __nv_bfloat16 g_xlo[(size_t)NSLOT*BATCH*DIMN];
__device__ __align__(1024) __nv_bfloat16 g_hhi[(size_t)NSLOT*BATCH*DIMN];
__device__ __align__(1024) __nv_bfloat16 g_hlo[(size_t)NSLOT*BATCH*DIMN];
__device__ __align__(1024) __nv_bfloat16 g_w1hi[(size_t)NSLOT*DIMN*DIMN];   // [n][k][d] K-major
__device__ __align__(1024) __nv_bfloat16 g_w1lo[(size_t)NSLOT*DIMN*DIMN];
__device__ __align__(1024) __nv_bfloat16 g_w2hi[(size_t)NSLOT*DIMN*DIMN];
__device__ __align__(1024) __nv_bfloat16 g_w2lo[(size_t)NSLOT*DIMN*DIMN];

// ---------------- PTX helpers (sm_90-level base ISA, valid on target sm_100) ----------------
__device__ __forceinline__ uint32_t smem_to_u32(const void* p) {
    uint32_t a;
    asm("{ .reg .u64 t; cvta.to.shared.u64 t, %1; cvt.u32.u64 %0, t; }" : "=r"(a) : "l"(p));
    return a;
}
#define CP_ASYNC16(dst, src) \
    asm volatile("cp.async.cg.shared.global [%0], [%1], 16;" :: "r"(dst), "l"(src))
#define CP_COMMIT() asm volatile("cp.async.commit_group;" ::: "memory")
#define CP_WAIT1()  asm volatile("cp.async.wait_group 1;" ::: "memory")

#define LDSM4(r0, r1, r2, r3, addr) \
    asm volatile("ldmatrix.sync.aligned.m8n8.x4.shared.b16 {%0,%1,%2,%3}, [%4];" \
        : "=r"(r0), "=r"(r1), "=r"(r2), "=r"(r3) : "r"(addr))

#define MMA16816(d, a, b) \
    asm volatile("mma.sync.aligned.m16n8k16.row.col.f32.bf16.bf16.f32 " \
        "{%0,%1,%2,%3}, {%4,%5,%6,%7}, {%8,%9}, {%0,%1,%2,%3};" \
        : "+f"((d)[0]), "+f"((d)[1]), "+f"((d)[2]), "+f"((d)[3]) \
        : "r"((a)[0]), "r"((a)[1]), "r"((a)[2]), "r"((a)[3]), "r"((b)[0]), "r"((b)[1]))

#define MBARRIER_INIT(mbar, count) \
    asm volatile("mbarrier.init.shared.b64 [%0], %1;" :: "r"((uint32_t)(mbar)), "r"((uint32_t)(count)) : "memory")
#define MBARRIER_EXPECT_TX(mbar, tx) \
    asm volatile("mbarrier.arrive.expect_tx.shared.b64 _, [%0], %1;" :: "r"((uint32_t)(mbar)), "r"((uint32_t)(tx)) : "memory")
#define MBARRIER_WAIT_PARITY(mbar, parity) do { \
    uint32_t _m = (uint32_t)(mbar); uint32_t _p = (uint32_t)(parity); uint32_t _d; \
    asm volatile("{\n\t.reg .pred p;\n\tmbarrier.try_wait.parity.acquire.cta.shared::cta.b64 p, [%1], %2;\n\tselp.b32 %0, 1, 0, p;\n\t}" \
        : "=r"(_d) : "r"(_m), "r"(_p) : "memory"); \
    if (!_d) { \
        asm volatile("{\n\t.reg .pred P1;\n\tWL_%=:\n\tmbarrier.try_wait.parity.acquire.cta.shared::cta.b64 P1, [%0], %1, 0x989680;\n\t@P1 bra.uni WD_%=;\n\tbra.uni WL_%=;\n\tWD_%=:\n\t}" \
            :: "r"(_m), "r"(_p) : "memory"); \
    } } while(0)
#define FENCE_PROXY_ASYNC() asm volatile("fence.proxy.async.shared::cta;" ::: "memory")

__device__ __forceinline__ void tma_load_2d(uint32_t smem, const void* map, int32_t cx, int32_t cy, uint32_t mbar) {
    asm volatile(
        "cp.async.bulk.tensor.2d.shared::cta.global.tile.mbarrier::complete_tx::bytes "
        "[%0], [%1, {%2, %3}], [%4];"
        :: "r"(smem), "l"(map), "r"(cx), "r"(cy), "r"(mbar) : "memory");
}

__device__ __forceinline__ void splitf(float v, __nv_bfloat16& h, __nv_bfloat16& l) {
    h = __float2bfloat16(v);
    l = __float2bfloat16(v - __bfloat162float(h));
}
__device__ __forceinline__ uint32_t pack_bf(__nv_bfloat16 a, __nv_bfloat16 b) {
    __nv_bfloat162 t; t.x = a; t.y = b;
    return *reinterpret_cast<uint32_t*>(&t);
}

// ---------------- LayerNorm + hi/lo split, [b][n][d] -> [n][b][d] ----------------
__global__ void __launch_bounds__(256) ln_split_kernel(
    const float* __restrict__ x, const float* __restrict__ gamma, const float* __restrict__ beta,
    __nv_bfloat16* __restrict__ xhi, __nv_bfloat16* __restrict__ xlo)
{
    int warp = threadIdx.x >> 5, lane = threadIdx.x & 31;
    long r = (long)blockIdx.x * 8 + warp;           // row = b*16+n
    int b = (int)(r >> 4), n = (int)(r & 15);
    const float4* xr = (const float4*)(x + (size_t)r * DIMN);
    float4 v[8]; float s = 0.f, ss = 0.f;
#pragma unroll
    for (int i = 0; i < 8; i++) {
        v[i] = xr[lane + 32 * i];
        s  += v[i].x + v[i].y + v[i].z + v[i].w;
        ss += v[i].x * v[i].x + v[i].y * v[i].y + v[i].z * v[i].z + v[i].w * v[i].w;
    }
#pragma unroll
    for (int o = 16; o > 0; o >>= 1) {
        s  += __shfl_xor_sync(0xFFFFFFFFu, s, o);
        ss += __shfl_xor_sync(0xFFFFFFFFu, ss, o);
    }
    float mu = s * (1.f / DIMN);
    float var = ss * (1.f / DIMN) - mu * mu;
    float rs = rsqrtf(var + 1e-5f);
    size_t ob = ((size_t)n * BATCH + b) * DIMN;
    uint2* oh = (uint2*)(xhi + ob); uint2* ol = (uint2*)(xlo + ob);
    const float* gm = gamma + (size_t)n * DIMN;
    const float* bt = beta  + (size_t)n * DIMN;
#pragma unroll
    for (int i = 0; i < 8; i++) {
        int d0 = (lane + 32 * i) * 4;
        float y0 = (v[i].x - mu) * rs * gm[d0 + 0] + bt[d0 + 0];
        float y1 = (v[i].y - mu) * rs * gm[d0 + 1] + bt[d0 + 1];
        float y2 = (v[i].z - mu) * rs * gm[d0 + 2] + bt[d0 + 2];
        float y3 = (v[i].w - mu) * rs * gm[d0 + 3] + bt[d0 + 3];
        __nv_bfloat16 h0,l0,h1,l1,h2,l2,h3,l3;
        splitf(y0,h0,l0); splitf(y1,h1,l1); splitf(y2,h2,l2); splitf(y3,h3,l3);
        uint2 ph, pl;
        ph.x = pack_bf(h0,h1); ph.y = pack_bf(h2,h3);
        pl.x = pack_bf(l0,l1); pl.y = pack_bf(l2,l3);
        oh[lane + 32 * i] = ph; ol[lane + 32 * i] = pl;
    }
}

// ---------------- W[n][d][k] -> Wt[n][k][d] hi/lo (transpose + split) ----------------
__global__ void __launch_bounds__(256) wprep_kernel(
    const float* __restrict__ W, __nv_bfloat16* __restrict__ hi, __nv_bfloat16* __restrict__ lo)
{
    __shared__ float t[32][33];
    int n = blockIdx.z;
    int d0 = blockIdx.x * 32, k0 = blockIdx.y * 32;
    const float* Wn = W + (size_t)n * DIMN * DIMN;
#pragma unroll
    for (int j = 0; j < 32; j += 8)
        t[threadIdx.y + j][threadIdx.x] = Wn[(size_t)(d0 + threadIdx.y + j) * DIMN + k0 + threadIdx.x];
    __syncthreads();
    size_t base = (size_t)n * DIMN * DIMN;
#pragma unroll
    for (int j = 0; j < 32; j += 8) {
        float vv = t[threadIdx.x][threadIdx.y + j];
        __nv_bfloat16 h, l; splitf(vv, h, l);
        size_t idx = base + (size_t)(k0 + threadIdx.y + j) * DIMN + d0 + threadIdx.x;
        hi[idx] = h; lo[idx] = l;
    }
}

// ---------------- shared GEMM geometry ----------------
#define BK 32
#define NCHUNK (DIMN / BK)          // 32
#define TILEB (128 * 64)            // 8192 bytes per operand tile
#define STAGEB (4 * TILEB)          // 32768
#define NSTAGE 3
#define SMEM_STAGES (NSTAGE * STAGEB)       // 98304
#define SMEM_GEMM (SMEM_STAGES + 64)        // + mbarriers

__device__ __forceinline__ uint32_t swz(uint32_t row, uint32_t chunk) {
    return row * 64 + ((chunk ^ ((row >> 1) & 3)) << 4);
}

// Common compute body for one chunk (identical for both load paths)
template<int EPI>
struct GemmCtx {};

__device__ __forceinline__ void compute_chunk(
    uint32_t stg, int warp_m, int warp_n, int lane, float acc[4][4][4])
{
    const uint32_t sAh = stg;
    const uint32_t sAl = stg + TILEB;
    const uint32_t sBh = stg + 2 * TILEB;
    const uint32_t sBl = stg + 3 * TILEB;
#pragma unroll
    for (int ks = 0; ks < 2; ks++) {
        uint32_t ah[4][4], al[4][4];
        const uint32_t ca = ks * 2 + (lane >> 4);
#pragma unroll
        for (int tm = 0; tm < 4; tm++) {
            uint32_t r = warp_m * 64 + tm * 16 + (lane & 15);
            LDSM4(ah[tm][0], ah[tm][1], ah[tm][2], ah[tm][3], sAh + swz(r, ca));
            LDSM4(al[tm][0], al[tm][1], al[tm][2], al[tm][3], sAl + swz(r, ca));
        }
        uint32_t bh[4][2], bl[4][2];
        const uint32_t cb = ks * 2 + ((lane >> 3) & 1);
#pragma unroll
        for (int g = 0; g < 2; g++) {
            uint32_t n = warp_n * 32 + g * 16 + (lane & 7) + ((lane >> 4) << 3);
            LDSM4(bh[2*g][0], bh[2*g][1], bh[2*g+1][0], bh[2*g+1][1], sBh + swz(n, cb));
            LDSM4(bl[2*g][0], bl[2*g][1], bl[2*g+1][0], bl[2*g+1][1], sBl + swz(n, cb));
        }
#pragma unroll
        for (int tm = 0; tm < 4; tm++)
#pragma unroll
            for (int f = 0; f < 4; f++) {
                MMA16816(acc[tm][f], ah[tm], bh[f]);
                MMA16816(acc[tm][f], ah[tm], bl[f]);
                MMA16816(acc[tm][f], al[tm], bh[f]);
            }
    }
}

template<int EPI>
__device__ __forceinline__ void epilogue(
    int mt, int nt, int slot, int warp_m, int warp_n, int lane,
    float acc[4][4][4], const float* __restrict__ bias,
    float* __restrict__ outF, __nv_bfloat16* __restrict__ outHi, __nv_bfloat16* __restrict__ outLo)
{
#pragma unroll
    for (int tm = 0; tm < 4; tm++) {
#pragma unroll
        for (int f = 0; f < 4; f++) {
            int grow = mt * 128 + warp_m * 64 + tm * 16 + (lane >> 2);
            int ncol = nt * 128 + warp_n * 32 + f * 8 + (lane & 3) * 2;
            float bia0 = __ldg(bias + (size_t)slot * DIMN + ncol);
            float bia1 = __ldg(bias + (size_t)slot * DIMN + ncol + 1);
            float v00 = acc[tm][f][0] + bia0, v01 = acc[tm][f][1] + bia1;
            float v10 = acc[tm][f][2] + bia0, v11 = acc[tm][f][3] + bia1;
            if (EPI == 1) {
                const float is2 = 0.70710678118654752f;
                v00 = 0.5f * v00 * (1.0f + erff(v00 * is2));
                v01 = 0.5f * v01 * (1.0f + erff(v01 * is2));
                v10 = 0.5f * v10 * (1.0f + erff(v10 * is2));
                v11 = 0.5f * v11 * (1.0f + erff(v11 * is2));
                __nv_bfloat16 h00,l00,h01,l01,h10,l10,h11,l11;
                splitf(v00,h00,l00); splitf(v01,h01,l01);
                splitf(v10,h10,l10); splitf(v11,h11,l11);
                size_t o0 = ((size_t)slot * BATCH + grow) * DIMN + ncol;
                size_t o1 = o0 + 8 * DIMN;
                *(uint32_t*)(outHi + o0) = pack_bf(h00, h01);
                *(uint32_t*)(outLo + o0) = pack_bf(l00, l01);
                *(uint32_t*)(outHi + o1) = pack_bf(h10, h11);
                *(uint32_t*)(outLo + o1) = pack_bf(l10, l11);
            } else {
                size_t o0 = ((size_t)grow * NSLOT + slot) * DIMN + ncol;
                size_t o1 = (((size_t)grow + 8) * NSLOT + slot) * DIMN + ncol;
                float2 w0; w0.x = v00; w0.y = v01;
                float2 w1; w1.x = v10; w1.y = v11;
                *(float2*)(outF + o0) = w0;
                *(float2*)(outF + o1) = w1;
            }
        }
    }
}

// ---------------- TMA-fed GEMM (primary path) ----------------
template<int EPI>
__global__ void __launch_bounds__(256, 2) gemm_tma_kernel(
    const __grid_constant__ CUtensorMap mAhi,
    const __grid_constant__ CUtensorMap mAlo,
    const __grid_constant__ CUtensorMap mBhi,
    const __grid_constant__ CUtensorMap mBlo,
    const float* __restrict__ bias,
    float* __restrict__ outF,
    __nv_bfloat16* __restrict__ outHi, __nv_bfloat16* __restrict__ outLo)
{
    extern __shared__ __align__(1024) char smem[];
    uint32_t sb = smem_to_u32(smem);
    const uint32_t mb = sb + SMEM_STAGES;             // 3 mbarriers, 8B each
    const int tid = threadIdx.x, wid = tid >> 5, lane = tid & 31;
    const int nt = blockIdx.x, mt = blockIdx.y, slot = blockIdx.z;
    const int warp_m = wid & 1, warp_n = wid >> 1;

    const int arow0 = slot * BATCH + mt * 128;
    const int brow0 = slot * DIMN  + nt * 128;

    if (tid == 0) {
        MBARRIER_INIT(mb,      1);
        MBARRIER_INIT(mb + 8,  1);
        MBARRIER_INIT(mb + 16, 1);
        FENCE_PROXY_ASYNC();
    }
    __syncthreads();

    auto fill = [&](int s, int c) {
        uint32_t bar = mb + 8 * s;
        uint32_t st  = sb + s * STAGEB;
        int k0 = c * BK;
        MBARRIER_EXPECT_TX(bar, (uint32_t)STAGEB);
        tma_load_2d(st,             &mAhi, k0, arow0, bar);
        tma_load_2d(st + TILEB,     &mAlo, k0, arow0, bar);
        tma_load_2d(st + 2 * TILEB, &mBhi, k0, brow0, bar);
        tma_load_2d(st + 3 * TILEB, &mBlo, k0, brow0, bar);
    };

    float acc[4][4][4];
#pragma unroll
    for (int tm = 0; tm < 4; tm++)
#pragma unroll
        for (int f = 0; f < 4; f++)
#pragma unroll
            for (int q = 0; q < 4; q++) acc[tm][f][q] = 0.f;

    if (tid == 0) { fill(0, 0); fill(1, 1); }

    for (int c = 0; c < NCHUNK; c++) {
        const int s = c % NSTAGE;
        // all warps finished chunk c-1 (stage (c+2)%3) before refilling it
        if (c > 0) __syncthreads();
        if (tid == 0 && c + 2 < NCHUNK) fill((c + 2) % NSTAGE, c + 2);
        MBARRIER_WAIT_PARITY(mb + 8 * s, (c / NSTAGE) & 1);
        compute_chunk(sb + s * STAGEB, warp_m, warp_n, lane, acc);
    }

    epilogue<EPI>(mt, nt, slot, warp_m, warp_n, lane, acc, bias, outF, outHi, outLo);
}

// ---------------- cp.async-fed GEMM (fallback if driver fn unavailable) ----------------
template<int EPI>
__global__ void __launch_bounds__(256, 2) gemm_cpasync_kernel(
    const __nv_bfloat16* __restrict__ Ahi, const __nv_bfloat16* __restrict__ Alo,
    const __nv_bfloat16* __restrict__ Bhi, const __nv_bfloat16* __restrict__ Blo,
    const float* __restrict__ bias,
    float* __restrict__ outF,
    __nv_bfloat16* __restrict__ outHi, __nv_bfloat16* __restrict__ outLo)
{
    extern __shared__ __align__(1024) char smem[];
    uint32_t sb = smem_to_u32(smem);
    const int tid = threadIdx.x, wid = tid >> 5, lane = tid & 31;
    const int nt = blockIdx.x, mt = blockIdx.y, slot = blockIdx.z;
    const int warp_m = wid & 1, warp_n = wid >> 1;

    const size_t arow0 = (size_t)slot * BATCH + (size_t)mt * 128;
    const size_t brow0 = (size_t)slot * DIMN  + (size_t)nt * 128;
    const __nv_bfloat16* srcs[4] = {
        Ahi + arow0 * DIMN, Alo + arow0 * DIMN,
        Bhi + brow0 * DIMN, Blo + brow0 * DIMN };

    auto fill = [&](int s, int c) {
#pragma unroll
        for (int j = 0; j < 8; j++) {
            int i = tid + j * 256;
            int tile = i >> 9;
            int row  = (i >> 2) & 127;
            int ch   = i & 3;
            uint32_t dst = sb + s * STAGEB + tile * TILEB + swz(row, ch);
            const __nv_bfloat16* src = srcs[tile] + (size_t)row * DIMN + c * BK + ch * 8;
            CP_ASYNC16(dst, src);
        }
    };

    float acc[4][4][4];
#pragma unroll
    for (int tm = 0; tm < 4; tm++)
#pragma unroll
        for (int f = 0; f < 4; f++)
#pragma unroll
            for (int q = 0; q < 4; q++) acc[tm][f][q] = 0.f;

    fill(0, 0); CP_COMMIT();
    fill(1, 1); CP_COMMIT();

    for (int c = 0; c < NCHUNK; c++) {
        CP_WAIT1();
        __syncthreads();
        if (c + 2 < NCHUNK) { fill((c + 2) % NSTAGE, c + 2); CP_COMMIT(); }
        compute_chunk(sb + (c % NSTAGE) * STAGEB, warp_m, warp_n, lane, acc);
    }

    epilogue<EPI>(mt, nt, slot, warp_m, warp_n, lane, acc, bias, outF, outHi, outLo);
}

// ---------------- host ----------------
typedef CUresult (*PFN_encodeTiled)(CUtensorMap*, CUtensorMapDataType, cuuint32_t, void*,
                                    const cuuint64_t*, const cuuint64_t*, const cuuint32_t*, const cuuint32_t*,
                                    CUtensorMapInterleave, CUtensorMapSwizzle, CUtensorMapL2promotion,
                                    CUtensorMapFloatOOBfill);

static bool make2d_bf16(PFN_encodeTiled fn, CUtensorMap* m, void* p, uint64_t rows) {
    cuuint64_t dims[2] = { DIMN, rows };
    cuuint64_t str[1]  = { DIMN * 2 };
    cuuint32_t box[2]  = { BK, 128 };        // 32 elems (64B) x 128 rows
    cuuint32_t es[2]   = { 1, 1 };
    return fn(m, CU_TENSOR_MAP_DATA_TYPE_BFLOAT16, 2, p, dims, str, box, es,
              CU_TENSOR_MAP_INTERLEAVE_NONE, CU_TENSOR_MAP_SWIZZLE_64B,
              CU_TENSOR_MAP_L2_PROMOTION_L2_128B, CU_TENSOR_MAP_FLOAT_OOB_FILL_NONE) == CUDA_SUCCESS;
}

extern "C" void kernel_launch(void* const* d_in, const int* in_sizes, int n_in,
                              void* d_out, int out_size) {
    (void)in_sizes; (void)n_in; (void)out_size;
    const float* x     = (const float*)d_in[0];
    const float* gamma = (const float*)d_in[1];
    const float* beta  = (const float*)d_in[2];
    const float* W1    = (const float*)d_in[3];
    const float* b1    = (const float*)d_in[4];
    const float* W2    = (const float*)d_in[5];
    const float* b2    = (const float*)d_in[6];
    float* out = (float*)d_out;

    void *pxhi, *pxlo, *phhi, *phlo, *pw1h, *pw1l, *pw2h, *pw2l;
    cudaGetSymbolAddress(&pxhi, g_xhi);  cudaGetSymbolAddress(&pxlo, g_xlo);
    cudaGetSymbolAddress(&phhi, g_hhi);  cudaGetSymbolAddress(&phlo, g_hlo);
    cudaGetSymbolAddress(&pw1h, g_w1hi); cudaGetSymbolAddress(&pw1l, g_w1lo);
    cudaGetSymbolAddress(&pw2h, g_w2hi); cudaGetSymbolAddress(&pw2l, g_w2lo);

    ln_split_kernel<<<(NSLOT * BATCH) / 8, 256>>>(x, gamma, beta,
        (__nv_bfloat16*)pxhi, (__nv_bfloat16*)pxlo);
    wprep_kernel<<<dim3(32, 32, NSLOT), dim3(32, 8)>>>(W1, (__nv_bfloat16*)pw1h, (__nv_bfloat16*)pw1l);
    wprep_kernel<<<dim3(32, 32, NSLOT), dim3(32, 8)>>>(W2, (__nv_bfloat16*)pw2h, (__nv_bfloat16*)pw2l);

    // resolve cuTensorMapEncodeTiled without -lcuda
    PFN_encodeTiled fn = nullptr;
    {
        cudaDriverEntryPointQueryResult st;
        unsigned int vers[3] = { 12000u, 12050u, 13000u };
        for (int i = 0; i < 3 && !fn; i++) {
            void* fp = nullptr;
            if (cudaGetDriverEntryPointByVersion("cuTensorMapEncodeTiled", &fp, vers[i],
                                                 cudaEnableDefault, &st) == cudaSuccess &&
                st == cudaDriverEntryPointSuccess && fp)
                fn = (PFN_encodeTiled)fp;
        }
    }

    dim3 grid(DIMN / 128, BATCH / 128, NSLOT);   // (8, 32, 16) = 4096 CTAs
    const uint64_t XROWS = (uint64_t)NSLOT * BATCH;   // 65536
    const uint64_t WROWS = (uint64_t)NSLOT * DIMN;    // 16384

    bool tma_ok = (fn != nullptr);
    CUtensorMap mXhi, mXlo, mW1h, mW1l, mHhi, mHlo, mW2h, mW2l;
    if (tma_ok) {
        tma_ok = make2d_bf16(fn, &mXhi, pxhi, XROWS) && make2d_bf16(fn, &mXlo, pxlo, XROWS)
              && make2d_bf16(fn, &mHhi, phhi, XROWS) && make2d_bf16(fn, &mHlo, phlo, XROWS)
              && make2d_bf16(fn, &mW1h, pw1h, WROWS) && make2d_bf16(fn, &mW1l, pw1l, WROWS)
              && make2d_bf16(fn, &mW2h, pw2h, WROWS) && make2d_bf16(fn, &mW2l, pw2l, WROWS);
    }

    if (tma_ok) {
        cudaFuncSetAttribute(gemm_tma_kernel<1>, cudaFuncAttributeMaxDynamicSharedMemorySize, SMEM_GEMM);
        cudaFuncSetAttribute(gemm_tma_kernel<2>, cudaFuncAttributeMaxDynamicSharedMemorySize, SMEM_GEMM);
        gemm_tma_kernel<1><<<grid, 256, SMEM_GEMM>>>(mXhi, mXlo, mW1h, mW1l,
            b1, nullptr, (__nv_bfloat16*)phhi, (__nv_bfloat16*)phlo);
        gemm_tma_kernel<2><<<grid, 256, SMEM_GEMM>>>(mHhi, mHlo, mW2h, mW2l,
            b2, out, nullptr, nullptr);
    } else {
        cudaFuncSetAttribute(gemm_cpasync_kernel<1>, cudaFuncAttributeMaxDynamicSharedMemorySize, SMEM_GEMM);
        cudaFuncSetAttribute(gemm_cpasync_kernel<2>, cudaFuncAttributeMaxDynamicSharedMemorySize, SMEM_GEMM);
        gemm_cpasync_kernel<1><<<grid, 256, SMEM_GEMM>>>(
            (const __nv_bfloat16*)pxhi, (const __nv_bfloat16*)pxlo,
            (const __nv_bfloat16*)pw1h, (const __nv_bfloat16*)pw1l,
            b1, nullptr, (__nv_bfloat16*)phhi, (__nv_bfloat16*)phlo);
        gemm_cpasync_kernel<2><<<grid, 256, SMEM_GEMM>>>(
            (const __nv_bfloat16*)phhi, (const __nv_bfloat16*)phlo,
            (const __nv_bfloat16*)pw2h, (const __nv_bfloat16*)pw2l,
            b2, out, nullptr, nullptr);
    }
}

// round 8
// speedup vs baseline: 1.3451x; 1.0576x over previous
#include <cuda_runtime.h>
#include <cuda.h>
#include <cuda_bf16.h>
#include <cstdint>

#define NSLOT 16
#define BATCH 4096
#define DIMN  1024

// ---------------- device scratch (allocation-free rule: __device__ globals) ----------------
__device__ __align__(1024) __nv_bfloat16 g_xhi[(size_t)NSLOT*BATCH*DIMN];
__device__ __align__(1024) __nv_bfloat16 g_xlo[(size_t)NSLOT*BATCH*DIMN];
__device__ __align__(1024) __nv_bfloat16 g_hhi[(size_t)NSLOT*BATCH*DIMN];
__device__ __align__(1024) __nv_bfloat16 g_hlo[(size_t)NSLOT*BATCH*DIMN];
__device__ __align__(1024) __nv_bfloat16 g_w1hi[(size_t)NSLOT*DIMN*DIMN];   // [n][k][d] K-major
__device__ __align__(1024) __nv_bfloat16 g_w1lo[(size_t)NSLOT*DIMN*DIMN];
__device__ __align__(1024) __nv_bfloat16 g_w2hi[(size_t)NSLOT*DIMN*DIMN];
__device__ __align__(1024) __nv_bfloat16 g_w2lo[(size_t)NSLOT*DIMN*DIMN];

// ---------------- PTX helpers (sm_90-level base ISA, valid on target sm_100) ----------------
__device__ __forceinline__ uint32_t smem_to_u32(const void* p) {
    uint32_t a;
    asm("{ .reg .u64 t; cvta.to.shared.u64 t, %1; cvt.u32.u64 %0, t; }" : "=r"(a) : "l"(p));
    return a;
}
#define CP_ASYNC16(dst, src) \
    asm volatile("cp.async.cg.shared.global [%0], [%1], 16;" :: "r"(dst), "l"(src))
#define CP_COMMIT() asm volatile("cp.async.commit_group;" ::: "memory")
#define CP_WAIT1()  asm volatile("cp.async.wait_group 1;" ::: "memory")

#define LDSM4(r0, r1, r2, r3, addr) \
    asm volatile("ldmatrix.sync.aligned.m8n8.x4.shared.b16 {%0,%1,%2,%3}, [%4];" \
        : "=r"(r0), "=r"(r1), "=r"(r2), "=r"(r3) : "r"(addr))

#define MMA16816(d, a, b) \
    asm volatile("mma.sync.aligned.m16n8k16.row.col.f32.bf16.bf16.f32 " \
        "{%0,%1,%2,%3}, {%4,%5,%6,%7}, {%8,%9}, {%0,%1,%2,%3};" \
        : "+f"((d)[0]), "+f"((d)[1]), "+f"((d)[2]), "+f"((d)[3]) \
        : "r"((a)[0]), "r"((a)[1]), "r"((a)[2]), "r"((a)[3]), "r"((b)[0]), "r"((b)[1]))

#define MBARRIER_INIT(mbar, count) \
    asm volatile("mbarrier.init.shared.b64 [%0], %1;" :: "r"((uint32_t)(mbar)), "r"((uint32_t)(count)) : "memory")
#define MBARRIER_EXPECT_TX(mbar, tx) \
    asm volatile("mbarrier.arrive.expect_tx.shared.b64 _, [%0], %1;" :: "r"((uint32_t)(mbar)), "r"((uint32_t)(tx)) : "memory")
#define MBARRIER_ARRIVE(mbar) \
    asm volatile("mbarrier.arrive.shared.b64 _, [%0];" :: "r"((uint32_t)(mbar)) : "memory")
#define MBARRIER_WAIT_PARITY(mbar, parity) do { \
    uint32_t _m = (uint32_t)(mbar); uint32_t _p = (uint32_t)(parity); uint32_t _d; \
    asm volatile("{\n\t.reg .pred p;\n\tmbarrier.try_wait.parity.acquire.cta.shared::cta.b64 p, [%1], %2;\n\tselp.b32 %0, 1, 0, p;\n\t}" \
        : "=r"(_d) : "r"(_m), "r"(_p) : "memory"); \
    if (!_d) { \
        asm volatile("{\n\t.reg .pred P1;\n\tWL_%=:\n\tmbarrier.try_wait.parity.acquire.cta.shared::cta.b64 P1, [%0], %1, 0x989680;\n\t@P1 bra.uni WD_%=;\n\tbra.uni WL_%=;\n\tWD_%=:\n\t}" \
            :: "r"(_m), "r"(_p) : "memory"); \
    } } while(0)
#define FENCE_PROXY_ASYNC() asm volatile("fence.proxy.async.shared::cta;" ::: "memory")

__device__ __forceinline__ void tma_load_2d(uint32_t smem, const void* map, int32_t cx, int32_t cy, uint32_t mbar) {
    asm volatile(
        "cp.async.bulk.tensor.2d.shared::cta.global.tile.mbarrier::complete_tx::bytes "
        "[%0], [%1, {%2, %3}], [%4];"
        :: "r"(smem), "l"(map), "r"(cx), "r"(cy), "r"(mbar) : "memory");
}

__device__ __forceinline__ void splitf(float v, __nv_bfloat16& h, __nv_bfloat16& l) {
    h = __float2bfloat16(v);
    l = __float2bfloat16(v - __bfloat162float(h));
}
__device__ __forceinline__ uint32_t pack_bf(__nv_bfloat16 a, __nv_bfloat16 b) {
    __nv_bfloat162 t; t.x = a; t.y = b;
    return *reinterpret_cast<uint32_t*>(&t);
}

// ---------------- LayerNorm + hi/lo split, [b][n][d] -> [n][b][d] ----------------
__global__ void __launch_bounds__(256) ln_split_kernel(
    const float* __restrict__ x, const float* __restrict__ gamma, const float* __restrict__ beta,
    __nv_bfloat16* __restrict__ xhi, __nv_bfloat16* __restrict__ xlo)
{
    int warp = threadIdx.x >> 5, lane = threadIdx.x & 31;
    long r = (long)blockIdx.x * 8 + warp;           // row = b*16+n
    int b = (int)(r >> 4), n = (int)(r & 15);
    const float4* xr = (const float4*)(x + (size_t)r * DIMN);
    float4 v[8]; float s = 0.f, ss = 0.f;
#pragma unroll
    for (int i = 0; i < 8; i++) {
        v[i] = xr[lane + 32 * i];
        s  += v[i].x + v[i].y + v[i].z + v[i].w;
        ss += v[i].x * v[i].x + v[i].y * v[i].y + v[i].z * v[i].z + v[i].w * v[i].w;
    }
#pragma unroll
    for (int o = 16; o > 0; o >>= 1) {
        s  += __shfl_xor_sync(0xFFFFFFFFu, s, o);
        ss += __shfl_xor_sync(0xFFFFFFFFu, ss, o);
    }
    float mu = s * (1.f / DIMN);
    float var = ss * (1.f / DIMN) - mu * mu;
    float rs = rsqrtf(var + 1e-5f);
    size_t ob = ((size_t)n * BATCH + b) * DIMN;
    uint2* oh = (uint2*)(xhi + ob); uint2* ol = (uint2*)(xlo + ob);
    const float* gm = gamma + (size_t)n * DIMN;
    const float* bt = beta  + (size_t)n * DIMN;
#pragma unroll
    for (int i = 0; i < 8; i++) {
        int d0 = (lane + 32 * i) * 4;
        float y0 = (v[i].x - mu) * rs * gm[d0 + 0] + bt[d0 + 0];
        float y1 = (v[i].y - mu) * rs * gm[d0 + 1] + bt[d0 + 1];
        float y2 = (v[i].z - mu) * rs * gm[d0 + 2] + bt[d0 + 2];
        float y3 = (v[i].w - mu) * rs * gm[d0 + 3] + bt[d0 + 3];
        __nv_bfloat16 h0,l0,h1,l1,h2,l2,h3,l3;
        splitf(y0,h0,l0); splitf(y1,h1,l1); splitf(y2,h2,l2); splitf(y3,h3,l3);
        uint2 ph, pl;
        ph.x = pack_bf(h0,h1); ph.y = pack_bf(h2,h3);
        pl.x = pack_bf(l0,l1); pl.y = pack_bf(l2,l3);
        oh[lane + 32 * i] = ph; ol[lane + 32 * i] = pl;
    }
}

// ---------------- W[n][d][k] -> Wt[n][k][d] hi/lo (transpose + split) ----------------
__global__ void __launch_bounds__(256) wprep_kernel(
    const float* __restrict__ W, __nv_bfloat16* __restrict__ hi, __nv_bfloat16* __restrict__ lo)
{
    __shared__ float t[32][33];
    int n = blockIdx.z;
    int d0 = blockIdx.x * 32, k0 = blockIdx.y * 32;
    const float* Wn = W + (size_t)n * DIMN * DIMN;
#pragma unroll
    for (int j = 0; j < 32; j += 8)
        t[threadIdx.y + j][threadIdx.x] = Wn[(size_t)(d0 + threadIdx.y + j) * DIMN + k0 + threadIdx.x];
    __syncthreads();
    size_t base = (size_t)n * DIMN * DIMN;
#pragma unroll
    for (int j = 0; j < 32; j += 8) {
        float vv = t[threadIdx.x][threadIdx.y + j];
        __nv_bfloat16 h, l; splitf(vv, h, l);
        size_t idx = base + (size_t)(k0 + threadIdx.y + j) * DIMN + d0 + threadIdx.x;
        hi[idx] = h; lo[idx] = l;
    }
}

// ---------------- shared GEMM geometry ----------------
#define BK 32
#define NCHUNK (DIMN / BK)          // 32
#define TILEB (128 * 64)            // 8192 bytes per operand tile
#define STAGEB (4 * TILEB)          // 32768
#define NSTAGE 3
#define SMEM_STAGES (NSTAGE * STAGEB)       // 98304
#define SMEM_GEMM (SMEM_STAGES + 64)        // + mbarriers (3 full + 3 empty)

__device__ __forceinline__ uint32_t swz(uint32_t row, uint32_t chunk) {
    return row * 64 + ((chunk ^ ((row >> 1) & 3)) << 4);
}

__device__ __forceinline__ void compute_chunk(
    uint32_t stg, int warp_m, int warp_n, int lane, float acc[4][4][4])
{
    const uint32_t sAh = stg;
    const uint32_t sAl = stg + TILEB;
    const uint32_t sBh = stg + 2 * TILEB;
    const uint32_t sBl = stg + 3 * TILEB;
#pragma unroll
    for (int ks = 0; ks < 2; ks++) {
        uint32_t ah[4][4], al[4][4];
        const uint32_t ca = ks * 2 + (lane >> 4);
#pragma unroll
        for (int tm = 0; tm < 4; tm++) {
            uint32_t r = warp_m * 64 + tm * 16 + (lane & 15);
            LDSM4(ah[tm][0], ah[tm][1], ah[tm][2], ah[tm][3], sAh + swz(r, ca));
            LDSM4(al[tm][0], al[tm][1], al[tm][2], al[tm][3], sAl + swz(r, ca));
        }
        uint32_t bh[4][2], bl[4][2];
        const uint32_t cb = ks * 2 + ((lane >> 3) & 1);
#pragma unroll
        for (int g = 0; g < 2; g++) {
            uint32_t n = warp_n * 32 + g * 16 + (lane & 7) + ((lane >> 4) << 3);
            LDSM4(bh[2*g][0], bh[2*g][1], bh[2*g+1][0], bh[2*g+1][1], sBh + swz(n, cb));
            LDSM4(bl[2*g][0], bl[2*g][1], bl[2*g+1][0], bl[2*g+1][1], sBl + swz(n, cb));
        }
#pragma unroll
        for (int tm = 0; tm < 4; tm++)
#pragma unroll
            for (int f = 0; f < 4; f++) {
                MMA16816(acc[tm][f], ah[tm], bh[f]);
                MMA16816(acc[tm][f], ah[tm], bl[f]);
                MMA16816(acc[tm][f], al[tm], bh[f]);
            }
    }
}

template<int EPI>
__device__ __forceinline__ void epilogue(
    int mt, int nt, int slot, int warp_m, int warp_n, int lane,
    float acc[4][4][4], const float* __restrict__ bias,
    float* __restrict__ outF, __nv_bfloat16* __restrict__ outHi, __nv_bfloat16* __restrict__ outLo)
{
#pragma unroll
    for (int tm = 0; tm < 4; tm++) {
#pragma unroll
        for (int f = 0; f < 4; f++) {
            int grow = mt * 128 + warp_m * 64 + tm * 16 + (lane >> 2);
            int ncol = nt * 128 + warp_n * 32 + f * 8 + (lane & 3) * 2;
            float bia0 = __ldg(bias + (size_t)slot * DIMN + ncol);
            float bia1 = __ldg(bias + (size_t)slot * DIMN + ncol + 1);
            float v00 = acc[tm][f][0] + bia0, v01 = acc[tm][f][1] + bia1;
            float v10 = acc[tm][f][2] + bia0, v11 = acc[tm][f][3] + bia1;
            if (EPI == 1) {
                const float is2 = 0.70710678118654752f;
                v00 = 0.5f * v00 * (1.0f + erff(v00 * is2));
                v01 = 0.5f * v01 * (1.0f + erff(v01 * is2));
                v10 = 0.5f * v10 * (1.0f + erff(v10 * is2));
                v11 = 0.5f * v11 * (1.0f + erff(v11 * is2));
                __nv_bfloat16 h00,l00,h01,l01,h10,l10,h11,l11;
                splitf(v00,h00,l00); splitf(v01,h01,l01);
                splitf(v10,h10,l10); splitf(v11,h11,l11);
                size_t o0 = ((size_t)slot * BATCH + grow) * DIMN + ncol;
                size_t o1 = o0 + 8 * DIMN;
                *(uint32_t*)(outHi + o0) = pack_bf(h00, h01);
                *(uint32_t*)(outLo + o0) = pack_bf(l00, l01);
                *(uint32_t*)(outHi + o1) = pack_bf(h10, h11);
                *(uint32_t*)(outLo + o1) = pack_bf(l10, l11);
            } else {
                size_t o0 = ((size_t)grow * NSLOT + slot) * DIMN + ncol;
                size_t o1 = (((size_t)grow + 8) * NSLOT + slot) * DIMN + ncol;
                float2 w0; w0.x = v00; w0.y = v01;
                float2 w1; w1.x = v10; w1.y = v11;
                *(float2*)(outF + o0) = w0;
                *(float2*)(outF + o1) = w1;
            }
        }
    }
}

// ---------------- TMA-fed GEMM, producer-consumer mbarrier pipeline ----------------
// full[s]: tx-barrier flipped by TMA.  empty[s]: 256 consumer arrivals gate refill.
// No per-chunk __syncthreads -> warps de-phase and keep the tensor pipe fed.
template<int EPI>
__global__ void __launch_bounds__(256, 2) gemm_tma_kernel(
    const __grid_constant__ CUtensorMap mAhi,
    const __grid_constant__ CUtensorMap mAlo,
    const __grid_constant__ CUtensorMap mBhi,
    const __grid_constant__ CUtensorMap mBlo,
    const float* __restrict__ bias,
    float* __restrict__ outF,
    __nv_bfloat16* __restrict__ outHi, __nv_bfloat16* __restrict__ outLo)
{
    extern __shared__ __align__(1024) char smem[];
    uint32_t sb = smem_to_u32(smem);
    const uint32_t mbF = sb + SMEM_STAGES;        // full[0..2], 8B each
    const uint32_t mbE = mbF + 24;                // empty[0..2], 8B each
    const int tid = threadIdx.x, wid = tid >> 5, lane = tid & 31;
    const int nt = blockIdx.x, mt = blockIdx.y, slot = blockIdx.z;
    const int warp_m = wid & 1, warp_n = wid >> 1;

    const int arow0 = slot * BATCH + mt * 128;
    const int brow0 = slot * DIMN  + nt * 128;

    if (tid == 0) {
#pragma unroll
        for (int s = 0; s < NSTAGE; s++) {
            MBARRIER_INIT(mbF + 8 * s, 1);
            MBARRIER_INIT(mbE + 8 * s, 256);
        }
        FENCE_PROXY_ASYNC();
    }
    __syncthreads();

    auto fill = [&](int s, int c) {
        uint32_t bar = mbF + 8 * s;
        uint32_t st  = sb + s * STAGEB;
        int k0 = c * BK;
        MBARRIER_EXPECT_TX(bar, (uint32_t)STAGEB);
        tma_load_2d(st,             &mAhi, k0, arow0, bar);
        tma_load_2d(st + TILEB,     &mAlo, k0, arow0, bar);
        tma_load_2d(st + 2 * TILEB, &mBhi, k0, brow0, bar);
        tma_load_2d(st + 3 * TILEB, &mBlo, k0, brow0, bar);
    };

    float acc[4][4][4];
#pragma unroll
    for (int tm = 0; tm < 4; tm++)
#pragma unroll
        for (int f = 0; f < 4; f++)
#pragma unroll
            for (int q = 0; q < 4; q++) acc[tm][f][q] = 0.f;

    if (tid == 0) { fill(0, 0); fill(1, 1); }

    for (int c = 0; c < NCHUNK; c++) {
        const int s = c % NSTAGE;
        if (tid == 0 && c + 2 < NCHUNK) {
            const int f = c + 2;
            // stage f%3 was consumed by chunk f-3; wait all 256 arrivals
            if (f >= NSTAGE)
                MBARRIER_WAIT_PARITY(mbE + 8 * (f % NSTAGE), ((f / NSTAGE) - 1) & 1);
            fill(f % NSTAGE, f);
        }
        MBARRIER_WAIT_PARITY(mbF + 8 * s, (c / NSTAGE) & 1);
        compute_chunk(sb + s * STAGEB, warp_m, warp_n, lane, acc);
        MBARRIER_ARRIVE(mbE + 8 * s);
    }

    epilogue<EPI>(mt, nt, slot, warp_m, warp_n, lane, acc, bias, outF, outHi, outLo);
}

// ---------------- cp.async-fed GEMM (fallback if driver fn unavailable) ----------------
template<int EPI>
__global__ void __launch_bounds__(256, 2) gemm_cpasync_kernel(
    const __nv_bfloat16* __restrict__ Ahi, const __nv_bfloat16* __restrict__ Alo,
    const __nv_bfloat16* __restrict__ Bhi, const __nv_bfloat16* __restrict__ Blo,
    const float* __restrict__ bias,
    float* __restrict__ outF,
    __nv_bfloat16* __restrict__ outHi, __nv_bfloat16* __restrict__ outLo)
{
    extern __shared__ __align__(1024) char smem[];
    uint32_t sb = smem_to_u32(smem);
    const int tid = threadIdx.x, wid = tid >> 5, lane = tid & 31;
    const int nt = blockIdx.x, mt = blockIdx.y, slot = blockIdx.z;
    const int warp_m = wid & 1, warp_n = wid >> 1;

    const size_t arow0 = (size_t)slot * BATCH + (size_t)mt * 128;
    const size_t brow0 = (size_t)slot * DIMN  + (size_t)nt * 128;
    const __nv_bfloat16* srcs[4] = {
        Ahi + arow0 * DIMN, Alo + arow0 * DIMN,
        Bhi + brow0 * DIMN, Blo + brow0 * DIMN };

    auto fill = [&](int s, int c) {
#pragma unroll
        for (int j = 0; j < 8; j++) {
            int i = tid + j * 256;
            int tile = i >> 9;
            int row  = (i >> 2) & 127;
            int ch   = i & 3;
            uint32_t dst = sb + s * STAGEB + tile * TILEB + swz(row, ch);
            const __nv_bfloat16* src = srcs[tile] + (size_t)row * DIMN + c * BK + ch * 8;
            CP_ASYNC16(dst, src);
        }
    };

    float acc[4][4][4];
#pragma unroll
    for (int tm = 0; tm < 4; tm++)
#pragma unroll
        for (int f = 0; f < 4; f++)
#pragma unroll
            for (int q = 0; q < 4; q++) acc[tm][f][q] = 0.f;

    fill(0, 0); CP_COMMIT();
    fill(1, 1); CP_COMMIT();

    for (int c = 0; c < NCHUNK; c++) {
        CP_WAIT1();
        __syncthreads();
        if (c + 2 < NCHUNK) { fill((c + 2) % NSTAGE, c + 2); CP_COMMIT(); }
        compute_chunk(sb + (c % NSTAGE) * STAGEB, warp_m, warp_n, lane, acc);
    }

    epilogue<EPI>(mt, nt, slot, warp_m, warp_n, lane, acc, bias, outF, outHi, outLo);
}

// ---------------- host ----------------
typedef CUresult (*PFN_encodeTiled)(CUtensorMap*, CUtensorMapDataType, cuuint32_t, void*,
                                    const cuuint64_t*, const cuuint64_t*, const cuuint32_t*, const cuuint32_t*,
                                    CUtensorMapInterleave, CUtensorMapSwizzle, CUtensorMapL2promotion,
                                    CUtensorMapFloatOOBfill);

static bool make2d_bf16(PFN_encodeTiled fn, CUtensorMap* m, void* p, uint64_t rows) {
    cuuint64_t dims[2] = { DIMN, rows };
    cuuint64_t str[1]  = { DIMN * 2 };
    cuuint32_t box[2]  = { BK, 128 };        // 32 elems (64B) x 128 rows
    cuuint32_t es[2]   = { 1, 1 };
    return fn(m, CU_TENSOR_MAP_DATA_TYPE_BFLOAT16, 2, p, dims, str, box, es,
              CU_TENSOR_MAP_INTERLEAVE_NONE, CU_TENSOR_MAP_SWIZZLE_64B,
              CU_TENSOR_MAP_L2_PROMOTION_L2_128B, CU_TENSOR_MAP_FLOAT_OOB_FILL_NONE) == CUDA_SUCCESS;
}

extern "C" void kernel_launch(void* const* d_in, const int* in_sizes, int n_in,
                              void* d_out, int out_size) {
    (void)in_sizes; (void)n_in; (void)out_size;
    const float* x     = (const float*)d_in[0];
    const float* gamma = (const float*)d_in[1];
    const float* beta  = (const float*)d_in[2];
    const float* W1    = (const float*)d_in[3];
    const float* b1    = (const float*)d_in[4];
    const float* W2    = (const float*)d_in[5];
    const float* b2    = (const float*)d_in[6];
    float* out = (float*)d_out;

    void *pxhi, *pxlo, *phhi, *phlo, *pw1h, *pw1l, *pw2h, *pw2l;
    cudaGetSymbolAddress(&pxhi, g_xhi);  cudaGetSymbolAddress(&pxlo, g_xlo);
    cudaGetSymbolAddress(&phhi, g_hhi);  cudaGetSymbolAddress(&phlo, g_hlo);
    cudaGetSymbolAddress(&pw1h, g_w1hi); cudaGetSymbolAddress(&pw1l, g_w1lo);
    cudaGetSymbolAddress(&pw2h, g_w2hi); cudaGetSymbolAddress(&pw2l, g_w2lo);

    ln_split_kernel<<<(NSLOT * BATCH) / 8, 256>>>(x, gamma, beta,
        (__nv_bfloat16*)pxhi, (__nv_bfloat16*)pxlo);
    wprep_kernel<<<dim3(32, 32, NSLOT), dim3(32, 8)>>>(W1, (__nv_bfloat16*)pw1h, (__nv_bfloat16*)pw1l);
    wprep_kernel<<<dim3(32, 32, NSLOT), dim3(32, 8)>>>(W2, (__nv_bfloat16*)pw2h, (__nv_bfloat16*)pw2l);

    PFN_encodeTiled fn = nullptr;
    {
        cudaDriverEntryPointQueryResult st;
        unsigned int vers[3] = { 12000u, 12050u, 13000u };
        for (int i = 0; i < 3 && !fn; i++) {
            void* fp = nullptr;
            if (cudaGetDriverEntryPointByVersion("cuTensorMapEncodeTiled", &fp, vers[i],
                                                 cudaEnableDefault, &st) == cudaSuccess &&
                st == cudaDriverEntryPointSuccess && fp)
                fn = (PFN_encodeTiled)fp;
        }
    }

    dim3 grid(DIMN / 128, BATCH / 128, NSLOT);   // (8, 32, 16) = 4096 CTAs
    const uint64_t XROWS = (uint64_t)NSLOT * BATCH;   // 65536
    const uint64_t WROWS = (uint64_t)NSLOT * DIMN;    // 16384

    bool tma_ok = (fn != nullptr);
    CUtensorMap mXhi, mXlo, mW1h, mW1l, mHhi, mHlo, mW2h, mW2l;
    if (tma_ok) {
        tma_ok = make2d_bf16(fn, &mXhi, pxhi, XROWS) && make2d_bf16(fn, &mXlo, pxlo, XROWS)
              && make2d_bf16(fn, &mHhi, phhi, XROWS) && make2d_bf16(fn, &mHlo, phlo, XROWS)
              && make2d_bf16(fn, &mW1h, pw1h, WROWS) && make2d_bf16(fn, &mW1l, pw1l, WROWS)
              && make2d_bf16(fn, &mW2h, pw2h, WROWS) && make2d_bf16(fn, &mW2l, pw2l, WROWS);
    }

    if (tma_ok) {
        cudaFuncSetAttribute(gemm_tma_kernel<1>, cudaFuncAttributeMaxDynamicSharedMemorySize, SMEM_GEMM);
        cudaFuncSetAttribute(gemm_tma_kernel<2>, cudaFuncAttributeMaxDynamicSharedMemorySize, SMEM_GEMM);
        gemm_tma_kernel<1><<<grid, 256, SMEM_GEMM>>>(mXhi, mXlo, mW1h, mW1l,
            b1, nullptr, (__nv_bfloat16*)phhi, (__nv_bfloat16*)phlo);
        gemm_tma_kernel<2><<<grid, 256, SMEM_GEMM>>>(mHhi, mHlo, mW2h, mW2l,
            b2, out, nullptr, nullptr);
    } else {
        cudaFuncSetAttribute(gemm_cpasync_kernel<1>, cudaFuncAttributeMaxDynamicSharedMemorySize, SMEM_GEMM);
        cudaFuncSetAttribute(gemm_cpasync_kernel<2>, cudaFuncAttributeMaxDynamicSharedMemorySize, SMEM_GEMM);
        gemm_cpasync_kernel<1><<<grid, 256, SMEM_GEMM>>>(
            (const __nv_bfloat16*)pxhi, (const __nv_bfloat16*)pxlo,
            (const __nv_bfloat16*)pw1h, (const __nv_bfloat16*)pw1l,
            b1, nullptr, (__nv_bfloat16*)phhi, (__nv_bfloat16*)phlo);
        gemm_cpasync_kernel<2><<<grid, 256, SMEM_GEMM>>>(
            (const __nv_bfloat16*)phhi, (const __nv_bfloat16*)phlo,
            (const __nv_bfloat16*)pw2h, (const __nv_bfloat16*)pw2l,
            b2, out, nullptr, nullptr);
    }
}